// round 9
// baseline (speedup 1.0000x reference)
#include <cuda_runtime.h>
#include <cuda_bf16.h>

// Chamfer distance via direct-insert uniform grid — 3 kernels, no grid
// barriers, no device fences. B=2, N=M=8192, C=3, coords ~U[0,1).
//
//  K1 insert:  point -> cell (CAP slots, overflow list). 1 atomic + 1 st.128.
//  K2 query:   one thread per query; 27 clamped neighbor-cell counts loaded
//              upfront (high MLP), stream points, register-accumulate the two
//              direction sums; deterministic per-CTA partials.
//  K3 final:   1 CTA sums partials in fixed order, writes (loss, rec_loss),
//              and re-zeros counts/overflow so graph replays are identical.
//
// Determinism: thread->query mapping fixed; in-thread/in-block/cross-block sum
// order fixed; atomic slot permutation only feeds fminf (permutation
// invariant) -> bitwise deterministic output.

#define G        16
#define NC       (G * G * G)
#define CAP      16
#define OVF_CAP  256
#define B_MAX    4
#define NSETS_MAX (2 * B_MAX)
#define BLK      128
#define MAXBLK   512

__device__ int    g_cnt [NSETS_MAX * NC];        // static zero; restored by K3
__device__ float4 g_cell[NSETS_MAX * NC * CAP];
__device__ int    g_ovf_cnt[NSETS_MAX];          // static zero; restored by K3
__device__ float4 g_ovf [NSETS_MAX * OVF_CAP];
__device__ float  g_p0[MAXBLK], g_p1[MAXBLK];

__device__ __forceinline__ int cell_of(float v) {
    int c = (int)(v * (float)G);
    return min(max(c, 0), G - 1);
}

__global__ __launch_bounds__(BLK)
void insert_kernel(const float* __restrict__ pos,
                   const float* __restrict__ xhat,
                   int N, int M, int B) {
    const int maxP = (N > M) ? N : M;
    const int j = blockIdx.x * BLK + threadIdx.x;
    const int sid = j / maxP;
    if (sid >= 2 * B) return;
    const int i     = j - sid * maxP;
    const int cloud = sid / B;
    const int b     = sid % B;
    const int n     = cloud ? M : N;
    if (i >= n) return;

    const float* p = (cloud ? xhat : pos) + ((size_t)b * n + i) * 3;
    const float x = p[0], y = p[1], z = p[2];
    const int cell = (cell_of(z) * G + cell_of(y)) * G + cell_of(x);
    const int slot = atomicAdd(&g_cnt[sid * NC + cell], 1);
    const float4 v = make_float4(x, y, z, x * x + y * y + z * z);
    if (slot < CAP) {
        g_cell[(sid * NC + cell) * CAP + slot] = v;
    } else {
        const int o = atomicAdd(&g_ovf_cnt[sid], 1);
        if (o < OVF_CAP) g_ovf[sid * OVF_CAP + o] = v;
    }
}

__global__ __launch_bounds__(BLK)
void query_kernel(const float* __restrict__ pos,
                  const float* __restrict__ xhat,
                  int N, int M, int B) {
    const int maxP = (N > M) ? N : M;
    const int j = blockIdx.x * BLK + threadIdx.x;

    float acc0 = 0.f, acc1 = 0.f;
    const int yb = j / maxP;

    if (yb < 2 * B) {
        const int i   = j - yb * maxP;
        const int dir = yb / B;
        const int b   = yb % B;
        const int nQ  = dir ? M : N;
        if (i < nQ) {
            const int sid_t = (1 - dir) * B + b;

            const float* qp = (dir ? xhat : pos) + ((size_t)b * nQ + i) * 3;
            const float qx = qp[0], qy = qp[1], qz = qp[2];
            const float qn = qx * qx + qy * qy + qz * qz;
            const float m2x = -2.0f * qx, m2y = -2.0f * qy, m2z = -2.0f * qz;
            const int cx = cell_of(qx), cy = cell_of(qy), cz = cell_of(qz);

            const int*    __restrict__ cnt  = g_cnt  + sid_t * NC;
            const float4* __restrict__ cell = g_cell + (size_t)sid_t * NC * CAP;
            const float h = 1.0f / (float)G;

            // 27 clamped neighbor cells; border duplicates harmless for min.
            int cb[27], cc[27];
#pragma unroll
            for (int s = 0; s < 27; ++s) {
                const int z = min(max(cz + s / 9 - 1, 0), G - 1);
                const int y = min(max(cy + (s / 3) % 3 - 1, 0), G - 1);
                const int x = min(max(cx + s % 3 - 1, 0), G - 1);
                const int c = (z * G + y) * G + x;
                cb[s] = c * CAP;
                cc[s] = cnt[c];      // independent loads -> one latency wave
            }

            float minAcc = 3.4e38f;
#pragma unroll
            for (int s = 0; s < 27; ++s) {
                const int c = min(cc[s], CAP);
                for (int k = 0; k < c; ++k) {
                    const float4 tt = cell[cb[s] + k];
                    const float d = fmaf(m2x, tt.x,
                                    fmaf(m2y, tt.y,
                                    fmaf(m2z, tt.z, tt.w)));
                    minAcc = fminf(minAcc, d);
                }
            }

            // overflow list (normally empty; covers any slot >= CAP)
            {
                const int no = min(g_ovf_cnt[sid_t], OVF_CAP);
                for (int k = 0; k < no; ++k) {
                    const float4 tt = g_ovf[sid_t * OVF_CAP + k];
                    const float d = fmaf(m2x, tt.x,
                                    fmaf(m2y, tt.y,
                                    fmaf(m2z, tt.z, tt.w)));
                    minAcc = fminf(minAcc, d);
                }
            }

            // r=1 termination bound; expand in the rare miss case
            const int x0 = max(cx - 1, 0), x1 = min(cx + 1, G - 1);
            const int y0 = max(cy - 1, 0), y1 = min(cy + 1, G - 1);
            const int z0 = max(cz - 1, 0), z1 = min(cz + 1, G - 1);
            float db = 3.4e38f;
            if (x0 > 0)     db = fminf(db, qx - (float)x0 * h);
            if (x1 < G - 1) db = fminf(db, (float)(x1 + 1) * h - qx);
            if (y0 > 0)     db = fminf(db, qy - (float)y0 * h);
            if (y1 < G - 1) db = fminf(db, (float)(y1 + 1) * h - qy);
            if (z0 > 0)     db = fminf(db, qz - (float)z0 * h);
            if (z1 < G - 1) db = fminf(db, (float)(z1 + 1) * h - qz);
            const bool full1 = (x0 == 0 && y0 == 0 && z0 == 0 &&
                                x1 == G - 1 && y1 == G - 1 && z1 == G - 1);

            if (!full1 && (qn + minAcc) > db * db) {
                int r = 2;
                while (true) {
                    const int ex0 = max(cx - r, 0), ex1 = min(cx + r, G - 1);
                    const int ey0 = max(cy - r, 0), ey1 = min(cy + r, G - 1);
                    const int ez0 = max(cz - r, 0), ez1 = min(cz + r, G - 1);
                    for (int z = ez0; z <= ez1; ++z)
                        for (int y = ey0; y <= ey1; ++y)
                            for (int x = ex0; x <= ex1; ++x) {
                                const int c  = (z * G + y) * G + x;
                                const int nc = min(cnt[c], CAP);
                                for (int k = 0; k < nc; ++k) {
                                    const float4 tt = cell[c * CAP + k];
                                    const float d = fmaf(m2x, tt.x,
                                                    fmaf(m2y, tt.y,
                                                    fmaf(m2z, tt.z, tt.w)));
                                    minAcc = fminf(minAcc, d);
                                }
                            }
                    float edb = 3.4e38f;
                    if (ex0 > 0)     edb = fminf(edb, qx - (float)ex0 * h);
                    if (ex1 < G - 1) edb = fminf(edb, (float)(ex1 + 1) * h - qx);
                    if (ey0 > 0)     edb = fminf(edb, qy - (float)ey0 * h);
                    if (ey1 < G - 1) edb = fminf(edb, (float)(ey1 + 1) * h - qy);
                    if (ez0 > 0)     edb = fminf(edb, qz - (float)ez0 * h);
                    if (ez1 < G - 1) edb = fminf(edb, (float)(ez1 + 1) * h - qz);
                    const bool ef = (ex0 == 0 && ey0 == 0 && ez0 == 0 &&
                                     ex1 == G - 1 && ey1 == G - 1 && ez1 == G - 1);
                    if (ef || (qn + minAcc) <= edb * edb) break;
                    ++r;
                }
            }

            const float dist = fmaxf(qn + minAcc, 0.0f);
            if (dir == 0) acc0 = dist; else acc1 = dist;
        }
    }

    // deterministic per-block partial sums
    __shared__ float red0[BLK / 32], red1[BLK / 32];
#pragma unroll
    for (int o = 16; o > 0; o >>= 1) {
        acc0 += __shfl_xor_sync(0xffffffffu, acc0, o);
        acc1 += __shfl_xor_sync(0xffffffffu, acc1, o);
    }
    if ((threadIdx.x & 31) == 0) {
        red0[threadIdx.x >> 5] = acc0;
        red1[threadIdx.x >> 5] = acc1;
    }
    __syncthreads();
    if (threadIdx.x == 0) {
        float s0 = 0.f, s1 = 0.f;
#pragma unroll
        for (int w = 0; w < BLK / 32; ++w) { s0 += red0[w]; s1 += red1[w]; }
        g_p0[blockIdx.x] = s0;
        g_p1[blockIdx.x] = s1;
    }
}

__global__ __launch_bounds__(256)
void finalize_kernel(float* __restrict__ out, int out_size,
                     int N, int M, int B, int nblocks) {
    // re-zero scratch for next graph replay
    {
        int4* cp = (int4*)g_cnt;
        const int n4 = (2 * B * NC) >> 2;
        for (int i = threadIdx.x; i < n4; i += 256)
            cp[i] = make_int4(0, 0, 0, 0);
        if (threadIdx.x < NSETS_MAX) g_ovf_cnt[threadIdx.x] = 0;
    }

    float s0 = 0.f, s1 = 0.f;
    for (int i = threadIdx.x; i < nblocks; i += 256) {
        s0 += g_p0[i];
        s1 += g_p1[i];
    }
    __shared__ float r0[8], r1[8];
#pragma unroll
    for (int o = 16; o > 0; o >>= 1) {
        s0 += __shfl_xor_sync(0xffffffffu, s0, o);
        s1 += __shfl_xor_sync(0xffffffffu, s1, o);
    }
    if ((threadIdx.x & 31) == 0) {
        r0[threadIdx.x >> 5] = s0;
        r1[threadIdx.x >> 5] = s1;
    }
    __syncthreads();
    if (threadIdx.x == 0) {
        float t0 = 0.f, t1 = 0.f;
#pragma unroll
        for (int w = 0; w < 8; ++w) { t0 += r0[w]; t1 += r1[w]; }
        const float rec = t0 / (float)((size_t)B * N) + t1 / (float)((size_t)B * M);
        for (int i = 0; i < out_size; ++i) out[i] = rec;   // (loss, rec_loss)
    }
}

extern "C" void kernel_launch(void* const* d_in, const int* in_sizes, int n_in,
                              void* d_out, int out_size) {
    const float* pos  = (const float*)d_in[0];
    const float* xhat = (const float*)d_in[1];

    const int B = 2;
    const int N = in_sizes[0] / (B * 3);
    const int M = in_sizes[1] / (B * 3);

    const int maxP  = (N > M) ? N : M;
    const int items = 2 * B * maxP;                 // 32768
    int nblocks = (items + BLK - 1) / BLK;          // 256
    if (nblocks > MAXBLK) nblocks = MAXBLK;         // (ample for these shapes)

    insert_kernel <<<nblocks, BLK>>>(pos, xhat, N, M, B);
    query_kernel  <<<nblocks, BLK>>>(pos, xhat, N, M, B);
    finalize_kernel<<<1, 256>>>((float*)d_out, out_size, N, M, B, nblocks);
}

// round 10
// speedup vs baseline: 1.1429x; 1.1429x over previous
#include <cuda_runtime.h>
#include <cuda_bf16.h>

// Chamfer distance via direct-insert uniform grid — 2 kernels.
// B=2, N=M=8192, C=3, coords ~U[0,1).
//
//  K1 insert: point -> cell (CAP slots, overflow list). 1 atomic + 1 st.128.
//  K2 query:  EIGHT threads per query (lane-group of 8). Each thread scans
//             3-4 of the 27 clamped neighbor cells (short critical path),
//             group-min via shfl_xor; role-0 lane handles overflow + rare
//             ring expansion + accumulation. Per-CTA partials; last-arriving
//             CTA sums them in fixed order, writes output, re-zeros counts.
//
// Determinism: fixed thread->query->cell mapping; fixed-order sums (thread,
// warp-butterfly, block, CTA-id order); atomic slot permutation only feeds
// fminf (permutation-invariant) -> bitwise deterministic. Scratch restored
// (counts, overflow, done) each run -> graph-replay invariant.

#define G        16
#define NC       (G * G * G)
#define CAP      16
#define OVF_CAP  256
#define B_MAX    4
#define NSETS_MAX (2 * B_MAX)
#define TPQ      8              // threads per query
#define BLK      128
#define MAXBLK   4096

__device__ int    g_cnt [NSETS_MAX * NC];        // static zero; restored
__device__ float4 g_cell[NSETS_MAX * NC * CAP];
__device__ int    g_ovf_cnt[NSETS_MAX];          // static zero; restored
__device__ float4 g_ovf [NSETS_MAX * OVF_CAP];
__device__ float  g_p0[MAXBLK], g_p1[MAXBLK];
__device__ unsigned int g_done = 0;

__device__ __forceinline__ int cell_of(float v) {
    int c = (int)(v * (float)G);
    return min(max(c, 0), G - 1);
}

__global__ __launch_bounds__(BLK)
void insert_kernel(const float* __restrict__ pos,
                   const float* __restrict__ xhat,
                   int N, int M, int B) {
    const int maxP = (N > M) ? N : M;
    const int j = blockIdx.x * BLK + threadIdx.x;
    const int sid = j / maxP;
    if (sid >= 2 * B) return;
    const int i     = j - sid * maxP;
    const int cloud = sid / B;
    const int b     = sid % B;
    const int n     = cloud ? M : N;
    if (i >= n) return;

    const float* p = (cloud ? xhat : pos) + ((size_t)b * n + i) * 3;
    const float x = p[0], y = p[1], z = p[2];
    const int cell = (cell_of(z) * G + cell_of(y)) * G + cell_of(x);
    const int slot = atomicAdd(&g_cnt[sid * NC + cell], 1);
    const float4 v = make_float4(x, y, z, x * x + y * y + z * z);
    if (slot < CAP) {
        g_cell[(sid * NC + cell) * CAP + slot] = v;
    } else {
        const int o = atomicAdd(&g_ovf_cnt[sid], 1);
        if (o < OVF_CAP) g_ovf[sid * OVF_CAP + o] = v;
    }
}

__global__ __launch_bounds__(BLK)
void query_kernel(const float* __restrict__ pos,
                  const float* __restrict__ xhat,
                  float* __restrict__ out, int out_size,
                  int N, int M, int B) {
    const int maxP = (N > M) ? N : M;
    const int j    = blockIdx.x * BLK + threadIdx.x;
    const int qq   = j / TPQ;          // query id (global)
    const int role = j % TPQ;          // 0..7 within the lane group

    float acc0 = 0.f, acc1 = 0.f;

    const int yb = qq / maxP;
    if (yb < 2 * B) {
        const int i   = qq - yb * maxP;
        const int dir = yb / B;
        const int b   = yb % B;
        const int nQ  = dir ? M : N;
        if (i < nQ) {
            const int sid_t = (1 - dir) * B + b;

            const float* qp = (dir ? xhat : pos) + ((size_t)b * nQ + i) * 3;
            const float qx = qp[0], qy = qp[1], qz = qp[2];
            const float qn = qx * qx + qy * qy + qz * qz;
            const float m2x = -2.0f * qx, m2y = -2.0f * qy, m2z = -2.0f * qz;
            const int cx = cell_of(qx), cy = cell_of(qy), cz = cell_of(qz);

            const int*    __restrict__ cnt  = g_cnt  + sid_t * NC;
            const float4* __restrict__ cell = g_cell + (size_t)sid_t * NC * CAP;
            const float h = 1.0f / (float)G;

            // This thread's cells: s = role, role+8, role+16, role+24 (<27).
            int cb[4], cc[4], nmy = 0;
#pragma unroll
            for (int k = 0; k < 4; ++k) {
                const int s = role + 8 * k;
                if (s < 27) {
                    const int z = min(max(cz + s / 9 - 1, 0), G - 1);
                    const int y = min(max(cy + (s / 3) % 3 - 1, 0), G - 1);
                    const int x = min(max(cx + s % 3 - 1, 0), G - 1);
                    const int c = (z * G + y) * G + x;
                    cb[nmy] = c * CAP;
                    cc[nmy] = cnt[c];       // independent loads
                    ++nmy;
                }
            }

            float minAcc = 3.4e38f;
#pragma unroll
            for (int k = 0; k < 4; ++k) {
                if (k < nmy) {
                    const int c = min(cc[k], CAP);
                    for (int t = 0; t < c; ++t) {
                        const float4 tt = cell[cb[k] + t];
                        const float d = fmaf(m2x, tt.x,
                                        fmaf(m2y, tt.y,
                                        fmaf(m2z, tt.z, tt.w)));
                        minAcc = fminf(minAcc, d);
                    }
                }
            }

            // overflow list (normally empty) — role 0 only
            if (role == 0) {
                const int no = min(g_ovf_cnt[sid_t], OVF_CAP);
                for (int k = 0; k < no; ++k) {
                    const float4 tt = g_ovf[sid_t * OVF_CAP + k];
                    const float d = fmaf(m2x, tt.x,
                                    fmaf(m2y, tt.y,
                                    fmaf(m2z, tt.z, tt.w)));
                    minAcc = fminf(minAcc, d);
                }
            }

            // group-of-8 min (lanes j..j+7 are one query)
            minAcc = fminf(minAcc, __shfl_xor_sync(0xffffffffu, minAcc, 4));
            minAcc = fminf(minAcc, __shfl_xor_sync(0xffffffffu, minAcc, 2));
            minAcc = fminf(minAcc, __shfl_xor_sync(0xffffffffu, minAcc, 1));

            if (role == 0) {
                // r=1 termination bound
                const int x0 = max(cx - 1, 0), x1 = min(cx + 1, G - 1);
                const int y0 = max(cy - 1, 0), y1 = min(cy + 1, G - 1);
                const int z0 = max(cz - 1, 0), z1 = min(cz + 1, G - 1);
                float db = 3.4e38f;
                if (x0 > 0)     db = fminf(db, qx - (float)x0 * h);
                if (x1 < G - 1) db = fminf(db, (float)(x1 + 1) * h - qx);
                if (y0 > 0)     db = fminf(db, qy - (float)y0 * h);
                if (y1 < G - 1) db = fminf(db, (float)(y1 + 1) * h - qy);
                if (z0 > 0)     db = fminf(db, qz - (float)z0 * h);
                if (z1 < G - 1) db = fminf(db, (float)(z1 + 1) * h - qz);
                const bool full1 = (x0 == 0 && y0 == 0 && z0 == 0 &&
                                    x1 == G - 1 && y1 == G - 1 && z1 == G - 1);

                if (!full1 && (qn + minAcc) > db * db) {
                    // rare: serial full-box rescan with growing radius
                    int r = 2;
                    while (true) {
                        const int ex0 = max(cx - r, 0), ex1 = min(cx + r, G - 1);
                        const int ey0 = max(cy - r, 0), ey1 = min(cy + r, G - 1);
                        const int ez0 = max(cz - r, 0), ez1 = min(cz + r, G - 1);
                        for (int z = ez0; z <= ez1; ++z)
                            for (int y = ey0; y <= ey1; ++y)
                                for (int x = ex0; x <= ex1; ++x) {
                                    const int c  = (z * G + y) * G + x;
                                    const int nc2 = min(cnt[c], CAP);
                                    for (int k = 0; k < nc2; ++k) {
                                        const float4 tt = cell[c * CAP + k];
                                        const float d = fmaf(m2x, tt.x,
                                                        fmaf(m2y, tt.y,
                                                        fmaf(m2z, tt.z, tt.w)));
                                        minAcc = fminf(minAcc, d);
                                    }
                                }
                        float edb = 3.4e38f;
                        if (ex0 > 0)     edb = fminf(edb, qx - (float)ex0 * h);
                        if (ex1 < G - 1) edb = fminf(edb, (float)(ex1 + 1) * h - qx);
                        if (ey0 > 0)     edb = fminf(edb, qy - (float)ey0 * h);
                        if (ey1 < G - 1) edb = fminf(edb, (float)(ey1 + 1) * h - qy);
                        if (ez0 > 0)     edb = fminf(edb, qz - (float)ez0 * h);
                        if (ez1 < G - 1) edb = fminf(edb, (float)(ez1 + 1) * h - qz);
                        const bool ef = (ex0 == 0 && ey0 == 0 && ez0 == 0 &&
                                         ex1 == G - 1 && ey1 == G - 1 && ez1 == G - 1);
                        if (ef || (qn + minAcc) <= edb * edb) break;
                        ++r;
                    }
                }

                const float dist = fmaxf(qn + minAcc, 0.0f);
                if (dir == 0) acc0 = dist; else acc1 = dist;
            }
        }
    }

    // ---- deterministic per-block partials ----
    __shared__ float red0[BLK / 32], red1[BLK / 32];
    __shared__ bool  amLast;
#pragma unroll
    for (int o = 16; o > 0; o >>= 1) {
        acc0 += __shfl_xor_sync(0xffffffffu, acc0, o);
        acc1 += __shfl_xor_sync(0xffffffffu, acc1, o);
    }
    if ((threadIdx.x & 31) == 0) {
        red0[threadIdx.x >> 5] = acc0;
        red1[threadIdx.x >> 5] = acc1;
    }
    __syncthreads();
    if (threadIdx.x == 0) {
        float s0 = 0.f, s1 = 0.f;
#pragma unroll
        for (int w = 0; w < BLK / 32; ++w) { s0 += red0[w]; s1 += red1[w]; }
        g_p0[blockIdx.x] = s0;
        g_p1[blockIdx.x] = s1;
        __threadfence();                                   // release partials
        amLast = (atomicAdd(&g_done, 1u) == gridDim.x - 1);
    }
    __syncthreads();

    // ---- last-arriving CTA: finalize + restore scratch ----
    if (amLast) {
        __threadfence();                                   // acquire partials
        float s0 = 0.f, s1 = 0.f;
        for (int i = threadIdx.x; i < (int)gridDim.x; i += BLK) {
            s0 += g_p0[i];
            s1 += g_p1[i];
        }
#pragma unroll
        for (int o = 16; o > 0; o >>= 1) {
            s0 += __shfl_xor_sync(0xffffffffu, s0, o);
            s1 += __shfl_xor_sync(0xffffffffu, s1, o);
        }
        if ((threadIdx.x & 31) == 0) {
            red0[threadIdx.x >> 5] = s0;
            red1[threadIdx.x >> 5] = s1;
        }
        __syncthreads();

        // restore scratch for next graph replay
        {
            int4* cp = (int4*)g_cnt;
            const int n4 = (2 * B * NC) >> 2;
            for (int i = threadIdx.x; i < n4; i += BLK)
                cp[i] = make_int4(0, 0, 0, 0);
            if (threadIdx.x < NSETS_MAX) g_ovf_cnt[threadIdx.x] = 0;
        }

        if (threadIdx.x == 0) {
            float t0 = 0.f, t1 = 0.f;
#pragma unroll
            for (int w = 0; w < BLK / 32; ++w) { t0 += red0[w]; t1 += red1[w]; }
            g_done = 0;
            const float rec = t0 / (float)((size_t)B * N) + t1 / (float)((size_t)B * M);
            for (int i = 0; i < out_size; ++i) out[i] = rec;   // (loss, rec_loss)
        }
    }
}

extern "C" void kernel_launch(void* const* d_in, const int* in_sizes, int n_in,
                              void* d_out, int out_size) {
    const float* pos  = (const float*)d_in[0];
    const float* xhat = (const float*)d_in[1];

    const int B = 2;
    const int N = in_sizes[0] / (B * 3);
    const int M = in_sizes[1] / (B * 3);

    const int maxP = (N > M) ? N : M;

    // K1: one thread per point
    {
        const int items = 2 * B * maxP;
        insert_kernel<<<(items + BLK - 1) / BLK, BLK>>>(pos, xhat, N, M, B);
    }
    // K2: TPQ threads per query (+fused finalize)
    {
        const int items = 2 * B * maxP * TPQ;
        int nblocks = (items + BLK - 1) / BLK;
        if (nblocks > MAXBLK) nblocks = MAXBLK;   // ample for these shapes
        query_kernel<<<nblocks, BLK>>>(pos, xhat, (float*)d_out, out_size, N, M, B);
    }
}